// round 2
// baseline (speedup 1.0000x reference)
#include <cuda_runtime.h>
#include <cstdint>

namespace {
constexpr int B_  = 2;
constexpr int S_  = 2048;
constexpr int D_  = 1024;
constexpr int H_  = 16;
constexpr int DK_ = 64;
}

// Scratch (allocation-free rule: __device__ globals)
__device__ float g_Q[B_ * S_ * D_];
__device__ float g_K[B_ * S_ * D_];
__device__ float g_V[B_ * S_ * D_];
__device__ float g_X[B_ * S_ * D_];

__device__ __forceinline__ uint32_t f2tf(float x) {
    uint32_t r;
    asm("cvt.rna.tf32.f32 %0, %1;" : "=r"(r) : "f"(x));
    return r;
}
__device__ __forceinline__ float f2tff(float x) { return __uint_as_float(f2tf(x)); }

__device__ __forceinline__ void mma_m16n8k8(float c[4],
                                            uint32_t a0, uint32_t a1, uint32_t a2, uint32_t a3,
                                            uint32_t b0, uint32_t b1) {
    asm volatile(
        "mma.sync.aligned.m16n8k8.row.col.f32.tf32.tf32.f32 "
        "{%0,%1,%2,%3}, {%4,%5,%6,%7}, {%8,%9}, {%0,%1,%2,%3};\n"
        : "+f"(c[0]), "+f"(c[1]), "+f"(c[2]), "+f"(c[3])
        : "r"(a0), "r"(a1), "r"(a2), "r"(a3), "r"(b0), "r"(b1));
}

#define CP_ASYNC16(dst_smem_u32, src_gmem_ptr) \
    asm volatile("cp.async.cg.shared.global [%0], [%1], 16;\n" \
                 :: "r"(dst_smem_u32), "l"(src_gmem_ptr))
#define CP_COMMIT() asm volatile("cp.async.commit_group;\n" ::: "memory")
#define CP_WAIT1()  asm volatile("cp.async.wait_group 1;\n" ::: "memory")
#define CP_WAIT0()  asm volatile("cp.async.wait_group 0;\n" ::: "memory")

// Shared-memory layout for the GEMM pipeline (floats):
//   stage s: A tile at s*STG_F,  B tile at s*STG_F + TA_F
namespace {
constexpr int LDT  = 36;          // smem row stride (conflict-free: bank = 4g+tg)
constexpr int TA_F = 128 * LDT;   // one 128x32 tile (padded)
constexpr int STG_F = 2 * TA_F;   // A+B per stage
constexpr int GEMM_SMEM_BYTES = 2 * STG_F * (int)sizeof(float);  // 73728
}

// C[M,N] = A[M,K] @ W[N,K]^T + bias[N]   (row-major fp32 in/out, tf32 MMA)
// 128x128 block tile, K-tile 32, 2-stage cp.async pipeline.
// 256 threads = 8 warps (2x4), warp tile 64x32.
__global__ __launch_bounds__(256) void gemm_nt_bias(
    const float* __restrict__ A, const float* __restrict__ W,
    const float* __restrict__ bias, float* __restrict__ C,
    int M, int N, int K)
{
    extern __shared__ float smem[];

    const int tid  = threadIdx.x;
    const int lane = tid & 31;
    const int warp = tid >> 5;
    const int g    = lane >> 2;
    const int tg   = lane & 3;
    const int wm   = warp >> 2;   // 0..1
    const int wn   = warp & 3;    // 0..3
    const int row0 = blockIdx.y * 128;
    const int col0 = blockIdx.x * 128;

    // Per-thread fixed slice of the cooperative tile load (4 rows x 1 float4 each
    // for A and B): lin = tid + i*256, r = lin>>3, c4 = (lin&7)*4.
    auto issue_stage = [&](int s, int k0) {
        #pragma unroll
        for (int i = 0; i < 4; i++) {
            int lin = tid + i * 256;
            int r   = lin >> 3;
            int c4  = (lin & 7) << 2;
            uint32_t da = (uint32_t)__cvta_generic_to_shared(&smem[s * STG_F + r * LDT + c4]);
            CP_ASYNC16(da, A + (size_t)(row0 + r) * K + k0 + c4);
            uint32_t db = (uint32_t)__cvta_generic_to_shared(&smem[s * STG_F + TA_F + r * LDT + c4]);
            CP_ASYNC16(db, W + (size_t)(col0 + r) * K + k0 + c4);
        }
        CP_COMMIT();
    };

    float acc[4][4][4];
    #pragma unroll
    for (int mt = 0; mt < 4; mt++)
        #pragma unroll
        for (int nt = 0; nt < 4; nt++)
            #pragma unroll
            for (int i = 0; i < 4; i++) acc[mt][nt][i] = 0.f;

    const int nk = K / 32;
    issue_stage(0, 0);

    for (int kt = 0; kt < nk; kt++) {
        const int cur = kt & 1;
        if (kt + 1 < nk) {
            issue_stage(cur ^ 1, (kt + 1) * 32);
            CP_WAIT1();           // current stage's group done; next still in flight
        } else {
            CP_WAIT0();
        }
        __syncthreads();

        const float* Acur = smem + cur * STG_F;
        const float* Bcur = smem + cur * STG_F + TA_F;

        #pragma unroll
        for (int kk = 0; kk < 32; kk += 8) {
            uint32_t af[4][4];
            uint32_t bf[4][2];
            #pragma unroll
            for (int mt = 0; mt < 4; mt++) {
                int r = wm * 64 + mt * 16 + g;
                af[mt][0] = f2tf(Acur[r * LDT + kk + tg]);
                af[mt][1] = f2tf(Acur[(r + 8) * LDT + kk + tg]);
                af[mt][2] = f2tf(Acur[r * LDT + kk + tg + 4]);
                af[mt][3] = f2tf(Acur[(r + 8) * LDT + kk + tg + 4]);
            }
            #pragma unroll
            for (int nt = 0; nt < 4; nt++) {
                int rr = wn * 32 + nt * 8 + g;
                bf[nt][0] = f2tf(Bcur[rr * LDT + kk + tg]);
                bf[nt][1] = f2tf(Bcur[rr * LDT + kk + tg + 4]);
            }
            #pragma unroll
            for (int mt = 0; mt < 4; mt++)
                #pragma unroll
                for (int nt = 0; nt < 4; nt++)
                    mma_m16n8k8(acc[mt][nt], af[mt][0], af[mt][1], af[mt][2], af[mt][3],
                                bf[nt][0], bf[nt][1]);
        }
        __syncthreads();   // protect cur from being overwritten by iter kt+1's issue
    }

    #pragma unroll
    for (int mt = 0; mt < 4; mt++) {
        int r = row0 + wm * 64 + mt * 16 + g;
        #pragma unroll
        for (int nt = 0; nt < 4; nt++) {
            int c = col0 + wn * 32 + nt * 8 + 2 * tg;
            float b0v = bias[c], b1v = bias[c + 1];
            float2 v0 = make_float2(acc[mt][nt][0] + b0v, acc[mt][nt][1] + b1v);
            float2 v1 = make_float2(acc[mt][nt][2] + b0v, acc[mt][nt][3] + b1v);
            *(float2*)(C + (size_t)r * N + c)       = v0;
            *(float2*)(C + (size_t)(r + 8) * N + c) = v1;
        }
    }
}

// Flash attention. One CTA = (b, h, 64-row q tile). 128 threads = 4 warps,
// each warp owns 16 q rows. Q/K/V are [B,S,H*DK] row-major (head-interleaved).
// X output in [B,S,H*DK] so the final projection is a plain GEMM.
__global__ __launch_bounds__(128) void attn_kernel(
    const float* __restrict__ Q, const float* __restrict__ Kc,
    const float* __restrict__ V, const int* __restrict__ mask,
    float* __restrict__ X)
{
    __shared__ float Ks[64][68];            // stride 68 -> conflict-free b-frag loads
    __shared__ float Vs[64][72];            // stride 72 -> conflict-free b-frag loads
    __shared__ unsigned char Ms[64][64];

    const int tid  = threadIdx.x;
    const int lane = tid & 31;
    const int warp = tid >> 5;
    const int g    = lane >> 2;
    const int tg   = lane & 3;

    const int h  = blockIdx.x;
    const int q0 = blockIdx.y * 64;
    const int b  = blockIdx.z;

    // Q fragments: registers for the entire KV loop (m16 x k64 per warp)
    uint32_t qf[8][4];
    {
        const int qrow = q0 + warp * 16 + g;
        const float* qp0 = Q + ((size_t)(b * S_ + qrow)) * D_ + h * DK_;
        const float* qp1 = qp0 + (size_t)8 * D_;
        #pragma unroll
        for (int kk = 0; kk < 8; kk++) {
            qf[kk][0] = f2tf(qp0[kk * 8 + tg]);
            qf[kk][1] = f2tf(qp1[kk * 8 + tg]);
            qf[kk][2] = f2tf(qp0[kk * 8 + tg + 4]);
            qf[kk][3] = f2tf(qp1[kk * 8 + tg + 4]);
        }
    }

    float oacc[8][4];
    #pragma unroll
    for (int nt = 0; nt < 8; nt++) {
        oacc[nt][0] = 0.f; oacc[nt][1] = 0.f; oacc[nt][2] = 0.f; oacc[nt][3] = 0.f;
    }
    float m0 = -1e30f, m1 = -1e30f, l0 = 0.f, l1 = 0.f;
    const int r0l = warp * 16 + g;   // local q row for c0/c1 (c2/c3 = +8)

    for (int j = 0; j < S_ / 64; j++) {
        const int k0 = j * 64;

        // Cooperative tile loads: K, V (tf32-rounded), mask (as bytes)
        #pragma unroll
        for (int i = 0; i < 8; i++) {
            int lin = tid + i * 128;
            int r   = lin >> 4;
            int c4  = (lin & 15) << 2;
            float4 kv = *(const float4*)(Kc + ((size_t)(b * S_ + k0 + r)) * D_ + h * DK_ + c4);
            kv.x = f2tff(kv.x); kv.y = f2tff(kv.y); kv.z = f2tff(kv.z); kv.w = f2tff(kv.w);
            *(float4*)&Ks[r][c4] = kv;
            float4 vv = *(const float4*)(V + ((size_t)(b * S_ + k0 + r)) * D_ + h * DK_ + c4);
            vv.x = f2tff(vv.x); vv.y = f2tff(vv.y); vv.z = f2tff(vv.z); vv.w = f2tff(vv.w);
            *(float4*)&Vs[r][c4] = vv;
            int4 mv = *(const int4*)(mask + (size_t)b * S_ * S_ + (size_t)(q0 + r) * S_ + k0 + c4);
            uchar4 mb;
            mb.x = (unsigned char)(mv.x > 0); mb.y = (unsigned char)(mv.y > 0);
            mb.z = (unsigned char)(mv.z > 0); mb.w = (unsigned char)(mv.w > 0);
            *(uchar4*)&Ms[r][c4] = mb;
        }
        __syncthreads();

        // S = Q @ K^T  (per warp: 16 x 64)
        float sacc[8][4];
        #pragma unroll
        for (int nt = 0; nt < 8; nt++) {
            sacc[nt][0] = 0.f; sacc[nt][1] = 0.f; sacc[nt][2] = 0.f; sacc[nt][3] = 0.f;
        }
        #pragma unroll
        for (int kk = 0; kk < 8; kk++) {
            #pragma unroll
            for (int nt = 0; nt < 8; nt++) {
                uint32_t b0 = __float_as_uint(Ks[nt * 8 + g][kk * 8 + tg]);
                uint32_t b1 = __float_as_uint(Ks[nt * 8 + g][kk * 8 + tg + 4]);
                mma_m16n8k8(sacc[nt], qf[kk][0], qf[kk][1], qf[kk][2], qf[kk][3], b0, b1);
            }
        }

        // scale + mask (-1000 exact, matching reference), online softmax
        float rmax0 = -1e30f, rmax1 = -1e30f;
        #pragma unroll
        for (int nt = 0; nt < 8; nt++) {
            int c = nt * 8 + 2 * tg;
            float s0 = Ms[r0l][c]         ? -1000.f : sacc[nt][0] * 0.125f;
            float s1 = Ms[r0l][c + 1]     ? -1000.f : sacc[nt][1] * 0.125f;
            float s2 = Ms[r0l + 8][c]     ? -1000.f : sacc[nt][2] * 0.125f;
            float s3 = Ms[r0l + 8][c + 1] ? -1000.f : sacc[nt][3] * 0.125f;
            sacc[nt][0] = s0; sacc[nt][1] = s1; sacc[nt][2] = s2; sacc[nt][3] = s3;
            rmax0 = fmaxf(rmax0, fmaxf(s0, s1));
            rmax1 = fmaxf(rmax1, fmaxf(s2, s3));
        }
        rmax0 = fmaxf(rmax0, __shfl_xor_sync(0xffffffffu, rmax0, 1));
        rmax0 = fmaxf(rmax0, __shfl_xor_sync(0xffffffffu, rmax0, 2));
        rmax1 = fmaxf(rmax1, __shfl_xor_sync(0xffffffffu, rmax1, 1));
        rmax1 = fmaxf(rmax1, __shfl_xor_sync(0xffffffffu, rmax1, 2));
        float mn0 = fmaxf(m0, rmax0);
        float mn1 = fmaxf(m1, rmax1);

        float rs0 = 0.f, rs1 = 0.f;
        #pragma unroll
        for (int nt = 0; nt < 8; nt++) {
            float p0 = __expf(sacc[nt][0] - mn0);
            float p1 = __expf(sacc[nt][1] - mn0);
            float p2 = __expf(sacc[nt][2] - mn1);
            float p3 = __expf(sacc[nt][3] - mn1);
            rs0 += p0 + p1;
            rs1 += p2 + p3;
            sacc[nt][0] = f2tff(p0); sacc[nt][1] = f2tff(p1);
            sacc[nt][2] = f2tff(p2); sacc[nt][3] = f2tff(p3);
        }
        rs0 += __shfl_xor_sync(0xffffffffu, rs0, 1);
        rs0 += __shfl_xor_sync(0xffffffffu, rs0, 2);
        rs1 += __shfl_xor_sync(0xffffffffu, rs1, 1);
        rs1 += __shfl_xor_sync(0xffffffffu, rs1, 2);

        float al0 = __expf(m0 - mn0);
        float al1 = __expf(m1 - mn1);
        l0 = l0 * al0 + rs0;
        l1 = l1 * al1 + rs1;
        m0 = mn0; m1 = mn1;
        #pragma unroll
        for (int nt = 0; nt < 8; nt++) {
            oacc[nt][0] *= al0; oacc[nt][1] *= al0;
            oacc[nt][2] *= al1; oacc[nt][3] *= al1;
        }

        // O += P @ V. P C-fragments -> A-fragments via warp shuffles (no smem stage).
        #pragma unroll
        for (int kk = 0; kk < 8; kk++) {
            int src = g * 4 + (tg >> 1);
            float p0 = __shfl_sync(0xffffffffu, sacc[kk][0], src);
            float p1 = __shfl_sync(0xffffffffu, sacc[kk][1], src);
            float p2 = __shfl_sync(0xffffffffu, sacc[kk][2], src);
            float p3 = __shfl_sync(0xffffffffu, sacc[kk][3], src);
            float u0 = __shfl_sync(0xffffffffu, sacc[kk][0], src + 2);
            float u1 = __shfl_sync(0xffffffffu, sacc[kk][1], src + 2);
            float u2 = __shfl_sync(0xffffffffu, sacc[kk][2], src + 2);
            float u3 = __shfl_sync(0xffffffffu, sacc[kk][3], src + 2);
            bool odd = tg & 1;
            uint32_t a0 = __float_as_uint(odd ? p1 : p0);
            uint32_t a1 = __float_as_uint(odd ? p3 : p2);
            uint32_t a2 = __float_as_uint(odd ? u1 : u0);
            uint32_t a3 = __float_as_uint(odd ? u3 : u2);
            #pragma unroll
            for (int nt = 0; nt < 8; nt++) {
                uint32_t b0 = __float_as_uint(Vs[kk * 8 + tg][nt * 8 + g]);
                uint32_t b1 = __float_as_uint(Vs[kk * 8 + tg + 4][nt * 8 + g]);
                mma_m16n8k8(oacc[nt], a0, a1, a2, a3, b0, b1);
            }
        }
        __syncthreads();
    }

    float inv0 = 1.f / l0;
    float inv1 = 1.f / l1;
    #pragma unroll
    for (int nt = 0; nt < 8; nt++) {
        int r = q0 + r0l;
        int c = h * DK_ + nt * 8 + 2 * tg;
        float2 v0 = make_float2(oacc[nt][0] * inv0, oacc[nt][1] * inv0);
        float2 v1 = make_float2(oacc[nt][2] * inv1, oacc[nt][3] * inv1);
        *(float2*)(X + ((size_t)(b * S_ + r)) * D_ + c)     = v0;
        *(float2*)(X + ((size_t)(b * S_ + r + 8)) * D_ + c) = v1;
    }
}

extern "C" void kernel_launch(void* const* d_in, const int* in_sizes, int n_in,
                              void* d_out, int out_size) {
    (void)in_sizes; (void)n_in; (void)out_size;
    const float* query = (const float*)d_in[0];
    const float* key   = (const float*)d_in[1];
    const float* value = (const float*)d_in[2];
    const int*   mask  = (const int*)d_in[3];
    const float* Wq = (const float*)d_in[4];
    const float* bq = (const float*)d_in[5];
    const float* Wk = (const float*)d_in[6];
    const float* bk = (const float*)d_in[7];
    const float* Wv = (const float*)d_in[8];
    const float* bv = (const float*)d_in[9];
    const float* Wo = (const float*)d_in[10];
    const float* bo = (const float*)d_in[11];
    float* out = (float*)d_out;

    float *pQ, *pK, *pV, *pX;
    cudaGetSymbolAddress((void**)&pQ, g_Q);
    cudaGetSymbolAddress((void**)&pK, g_K);
    cudaGetSymbolAddress((void**)&pV, g_V);
    cudaGetSymbolAddress((void**)&pX, g_X);

    static bool attr_done = false;
    if (!attr_done) {
        cudaFuncSetAttribute(gemm_nt_bias,
                             cudaFuncAttributeMaxDynamicSharedMemorySize,
                             GEMM_SMEM_BYTES);
        attr_done = true;
    }

    const int M = B_ * S_;
    dim3 gg(D_ / 128, M / 128);
    gemm_nt_bias<<<gg, 256, GEMM_SMEM_BYTES>>>(query, Wq, bq, pQ, M, D_, D_);
    gemm_nt_bias<<<gg, 256, GEMM_SMEM_BYTES>>>(key,   Wk, bk, pK, M, D_, D_);
    gemm_nt_bias<<<gg, 256, GEMM_SMEM_BYTES>>>(value, Wv, bv, pV, M, D_, D_);
    attn_kernel<<<dim3(H_, S_ / 64, B_), 128>>>(pQ, pK, pV, mask, pX);
    gemm_nt_bias<<<gg, 256, GEMM_SMEM_BYTES>>>(pX, Wo, bo, out, M, D_, D_);
}

// round 4
// speedup vs baseline: 1.6324x; 1.6324x over previous
#include <cuda_runtime.h>
#include <cstdint>

namespace {
constexpr int B_  = 2;
constexpr int S_  = 2048;
constexpr int D_  = 1024;
constexpr int H_  = 16;
constexpr int DK_ = 64;
}

// Scratch (allocation-free rule: __device__ globals)
__device__ float g_Q[B_ * S_ * D_];
__device__ float g_K[B_ * S_ * D_];
__device__ float g_V[B_ * S_ * D_];
__device__ float g_X[B_ * S_ * D_];
__device__ uint32_t g_Mb[(B_ * S_ * S_) / 32];   // bit-packed mask

__device__ __forceinline__ uint32_t f2tf(float x) {
    uint32_t r;
    asm("cvt.rna.tf32.f32 %0, %1;" : "=r"(r) : "f"(x));
    return r;
}
__device__ __forceinline__ float f2tff(float x) { return __uint_as_float(f2tf(x)); }

__device__ __forceinline__ void mma_m16n8k8(float c[4],
                                            uint32_t a0, uint32_t a1, uint32_t a2, uint32_t a3,
                                            uint32_t b0, uint32_t b1) {
    asm volatile(
        "mma.sync.aligned.m16n8k8.row.col.f32.tf32.tf32.f32 "
        "{%0,%1,%2,%3}, {%4,%5,%6,%7}, {%8,%9}, {%0,%1,%2,%3};\n"
        : "+f"(c[0]), "+f"(c[1]), "+f"(c[2]), "+f"(c[3])
        : "r"(a0), "r"(a1), "r"(a2), "r"(a3), "r"(b0), "r"(b1));
}

#define CP_ASYNC16(dst_smem_u32, src_gmem_ptr) \
    asm volatile("cp.async.cg.shared.global [%0], [%1], 16;\n" \
                 :: "r"(dst_smem_u32), "l"(src_gmem_ptr))
#define CP_ASYNC8(dst_smem_u32, src_gmem_ptr) \
    asm volatile("cp.async.ca.shared.global [%0], [%1], 8;\n" \
                 :: "r"(dst_smem_u32), "l"(src_gmem_ptr))
#define CP_COMMIT() asm volatile("cp.async.commit_group;\n" ::: "memory")
#define CP_WAIT1()  asm volatile("cp.async.wait_group 1;\n" ::: "memory")
#define CP_WAIT0()  asm volatile("cp.async.wait_group 0;\n" ::: "memory")

// ---------------------------------------------------------------------------
// Mask bit-pack: g_Mb bit j of word w corresponds to mask[32w + j] > 0.
__global__ __launch_bounds__(256) void pack_mask_kernel(
    const int* __restrict__ mask, uint32_t* __restrict__ out)
{
    int idx = blockIdx.x * 256 + threadIdx.x;
    int v = mask[idx] > 0 ? 1 : 0;
    uint32_t bal = __ballot_sync(0xffffffffu, v);
    if ((threadIdx.x & 31) == 0) out[idx >> 5] = bal;
}

// ---------------------------------------------------------------------------
// GEMM: C[M,N] = A[M,K] @ W[N,K]^T + bias[N]  (tf32 MMA, cp.async 2-stage).
// blockIdx.z selects one of up to 3 independent (A,W,bias,C) problems.
// round_out!=0 -> outputs rounded to tf32 (rna) so downstream MMA consumption
// of the raw fp32 bits is exact.
namespace {
constexpr int LDT  = 36;          // smem row stride (conflict-free frag reads)
constexpr int TA_F = 128 * LDT;
constexpr int STG_F = 2 * TA_F;
constexpr int GEMM_SMEM_BYTES = 2 * STG_F * (int)sizeof(float);  // 73728
}

__global__ __launch_bounds__(256) void gemm3_nt_bias(
    const float* __restrict__ A0, const float* __restrict__ A1, const float* __restrict__ A2,
    const float* __restrict__ W0, const float* __restrict__ W1, const float* __restrict__ W2,
    const float* __restrict__ bb0, const float* __restrict__ bb1, const float* __restrict__ bb2,
    float* __restrict__ C0, float* __restrict__ C1, float* __restrict__ C2,
    int M, int N, int K, int round_out)
{
    extern __shared__ float smem[];

    const int z = blockIdx.z;
    const float* A    = (z == 0) ? A0 : (z == 1) ? A1 : A2;
    const float* W    = (z == 0) ? W0 : (z == 1) ? W1 : W2;
    const float* bias = (z == 0) ? bb0 : (z == 1) ? bb1 : bb2;
    float*       C    = (z == 0) ? C0 : (z == 1) ? C1 : C2;

    const int tid  = threadIdx.x;
    const int lane = tid & 31;
    const int warp = tid >> 5;
    const int g    = lane >> 2;
    const int tg   = lane & 3;
    const int wm   = warp >> 2;
    const int wn   = warp & 3;
    const int row0 = blockIdx.y * 128;
    const int col0 = blockIdx.x * 128;

    auto issue_stage = [&](int s, int k0) {
        #pragma unroll
        for (int i = 0; i < 4; i++) {
            int lin = tid + i * 256;
            int r   = lin >> 3;
            int c4  = (lin & 7) << 2;
            uint32_t da = (uint32_t)__cvta_generic_to_shared(&smem[s * STG_F + r * LDT + c4]);
            CP_ASYNC16(da, A + (size_t)(row0 + r) * K + k0 + c4);
            uint32_t db = (uint32_t)__cvta_generic_to_shared(&smem[s * STG_F + TA_F + r * LDT + c4]);
            CP_ASYNC16(db, W + (size_t)(col0 + r) * K + k0 + c4);
        }
        CP_COMMIT();
    };

    float acc[4][4][4];
    #pragma unroll
    for (int mt = 0; mt < 4; mt++)
        #pragma unroll
        for (int nt = 0; nt < 4; nt++)
            #pragma unroll
            for (int i = 0; i < 4; i++) acc[mt][nt][i] = 0.f;

    const int nk = K / 32;
    issue_stage(0, 0);

    for (int kt = 0; kt < nk; kt++) {
        const int cur = kt & 1;
        if (kt + 1 < nk) {
            issue_stage(cur ^ 1, (kt + 1) * 32);
            CP_WAIT1();
        } else {
            CP_WAIT0();
        }
        __syncthreads();

        const float* Acur = smem + cur * STG_F;
        const float* Bcur = smem + cur * STG_F + TA_F;

        #pragma unroll
        for (int kk = 0; kk < 32; kk += 8) {
            uint32_t af[4][4];
            uint32_t bf[4][2];
            #pragma unroll
            for (int mt = 0; mt < 4; mt++) {
                int r = wm * 64 + mt * 16 + g;
                af[mt][0] = f2tf(Acur[r * LDT + kk + tg]);
                af[mt][1] = f2tf(Acur[(r + 8) * LDT + kk + tg]);
                af[mt][2] = f2tf(Acur[r * LDT + kk + tg + 4]);
                af[mt][3] = f2tf(Acur[(r + 8) * LDT + kk + tg + 4]);
            }
            #pragma unroll
            for (int nt = 0; nt < 4; nt++) {
                int rr = wn * 32 + nt * 8 + g;
                bf[nt][0] = f2tf(Bcur[rr * LDT + kk + tg]);
                bf[nt][1] = f2tf(Bcur[rr * LDT + kk + tg + 4]);
            }
            #pragma unroll
            for (int mt = 0; mt < 4; mt++)
                #pragma unroll
                for (int nt = 0; nt < 4; nt++)
                    mma_m16n8k8(acc[mt][nt], af[mt][0], af[mt][1], af[mt][2], af[mt][3],
                                bf[nt][0], bf[nt][1]);
        }
        __syncthreads();
    }

    #pragma unroll
    for (int mt = 0; mt < 4; mt++) {
        int r = row0 + wm * 64 + mt * 16 + g;
        #pragma unroll
        for (int nt = 0; nt < 4; nt++) {
            int c = col0 + wn * 32 + nt * 8 + 2 * tg;
            float b0v = bias[c], b1v = bias[c + 1];
            float o00 = acc[mt][nt][0] + b0v, o01 = acc[mt][nt][1] + b1v;
            float o10 = acc[mt][nt][2] + b0v, o11 = acc[mt][nt][3] + b1v;
            if (round_out) {
                o00 = f2tff(o00); o01 = f2tff(o01);
                o10 = f2tff(o10); o11 = f2tff(o11);
            }
            *(float2*)(C + (size_t)r * N + c)       = make_float2(o00, o01);
            *(float2*)(C + (size_t)(r + 8) * N + c) = make_float2(o10, o11);
        }
    }
}

// ---------------------------------------------------------------------------
// Flash attention. One CTA = (b, h, 64-row q tile). 128 threads = 4 warps.
// Q/K/V pre-rounded to tf32 by the QKV GEMM epilogue -> no cvt here.
// cp.async double-buffered K/V tiles + bit-packed mask rows.
namespace {
constexpr int AK_ST = 64 * 68;                 // K stage floats (stride 68: bank 4g+tg)
constexpr int AV_ST = 64 * 72;                 // V stage floats (stride 72: bank 8tg+g)
constexpr int A_KS_OFF = 0;
constexpr int A_VS_OFF = 2 * AK_ST;
constexpr int A_MB_OFF = A_VS_OFF + 2 * AV_ST; // floats
constexpr int ATTN_SMEM_BYTES = (A_MB_OFF + 2 * 64 * 2) * (int)sizeof(float); // 72704
}

__global__ __launch_bounds__(128, 3) void attn_kernel(
    const float* __restrict__ Q, const float* __restrict__ Kc,
    const float* __restrict__ V, const uint32_t* __restrict__ mbits,
    float* __restrict__ X)
{
    extern __shared__ float sm[];
    float* KsB = sm + A_KS_OFF;
    float* VsB = sm + A_VS_OFF;
    uint32_t* MbB = (uint32_t*)(sm + A_MB_OFF);

    const int tid  = threadIdx.x;
    const int lane = tid & 31;
    const int warp = tid >> 5;
    const int g    = lane >> 2;
    const int tg   = lane & 3;

    const int h  = blockIdx.x;
    const int q0 = blockIdx.y * 64;
    const int b  = blockIdx.z;

    auto issue_stage = [&](int st, int k0) {
        #pragma unroll
        for (int i = 0; i < 8; i++) {
            int lin = tid + i * 128;
            int r   = lin >> 4;
            int c4  = (lin & 15) << 2;
            const size_t gro = ((size_t)(b * S_ + k0 + r)) * D_ + h * DK_ + c4;
            uint32_t dk = (uint32_t)__cvta_generic_to_shared(&KsB[st * AK_ST + r * 68 + c4]);
            CP_ASYNC16(dk, Kc + gro);
            uint32_t dv = (uint32_t)__cvta_generic_to_shared(&VsB[st * AV_ST + r * 72 + c4]);
            CP_ASYNC16(dv, V + gro);
        }
        if (tid < 64) {
            uint32_t dm = (uint32_t)__cvta_generic_to_shared(&MbB[st * 128 + tid * 2]);
            CP_ASYNC8(dm, mbits + ((size_t)(b * S_ + q0 + tid)) * 64 + (k0 >> 5));
        }
        CP_COMMIT();
    };

    // Q fragments: registers for the entire KV loop (m16 x k64 per warp).
    uint32_t qf[8][4];
    {
        const int qrow = q0 + warp * 16 + g;
        const float* qp0 = Q + ((size_t)(b * S_ + qrow)) * D_ + h * DK_;
        const float* qp1 = qp0 + (size_t)8 * D_;
        #pragma unroll
        for (int kk = 0; kk < 8; kk++) {
            qf[kk][0] = __float_as_uint(qp0[kk * 8 + tg]);
            qf[kk][1] = __float_as_uint(qp1[kk * 8 + tg]);
            qf[kk][2] = __float_as_uint(qp0[kk * 8 + tg + 4]);
            qf[kk][3] = __float_as_uint(qp1[kk * 8 + tg + 4]);
        }
    }

    float oacc[8][4];
    #pragma unroll
    for (int nt = 0; nt < 8; nt++) {
        oacc[nt][0] = 0.f; oacc[nt][1] = 0.f; oacc[nt][2] = 0.f; oacc[nt][3] = 0.f;
    }
    float m0 = -1e30f, m1 = -1e30f, l0 = 0.f, l1 = 0.f;
    const int r0l = warp * 16 + g;

    constexpr int NJ = S_ / 64;
    issue_stage(0, 0);

    for (int j = 0; j < NJ; j++) {
        const int cur = j & 1;
        if (j + 1 < NJ) {
            issue_stage(cur ^ 1, (j + 1) * 64);
            CP_WAIT1();
        } else {
            CP_WAIT0();
        }
        __syncthreads();

        const float* Kcur = KsB + cur * AK_ST;
        const float* Vcur = VsB + cur * AV_ST;
        const uint32_t* Mcur = MbB + cur * 128;

        // S = Q @ K^T  (per warp: 16 x 64)
        float sacc[8][4];
        #pragma unroll
        for (int nt = 0; nt < 8; nt++) {
            sacc[nt][0] = 0.f; sacc[nt][1] = 0.f; sacc[nt][2] = 0.f; sacc[nt][3] = 0.f;
        }
        #pragma unroll
        for (int kk = 0; kk < 8; kk++) {
            #pragma unroll
            for (int nt = 0; nt < 8; nt++) {
                uint32_t b0 = __float_as_uint(Kcur[(nt * 8 + g) * 68 + kk * 8 + tg]);
                uint32_t b1 = __float_as_uint(Kcur[(nt * 8 + g) * 68 + kk * 8 + tg + 4]);
                mma_m16n8k8(sacc[nt], qf[kk][0], qf[kk][1], qf[kk][2], qf[kk][3], b0, b1);
            }
        }

        // Mask bits for my two q rows (broadcast LDS, conflict-free)
        const uint32_t w0a = Mcur[r0l * 2],       w0b = Mcur[r0l * 2 + 1];
        const uint32_t w1a = Mcur[(r0l + 8) * 2], w1b = Mcur[(r0l + 8) * 2 + 1];

        // scale + mask (-1000 exact), online softmax
        float rmax0 = -1e30f, rmax1 = -1e30f;
        #pragma unroll
        for (int nt = 0; nt < 8; nt++) {
            int c  = nt * 8 + 2 * tg;
            int sh = c & 31;
            uint32_t wa = (nt < 4) ? w0a : w0b;
            uint32_t wb = (nt < 4) ? w1a : w1b;
            float s0 = ((wa >> sh) & 1u)       ? -1000.f : sacc[nt][0] * 0.125f;
            float s1 = ((wa >> (sh + 1)) & 1u) ? -1000.f : sacc[nt][1] * 0.125f;
            float s2 = ((wb >> sh) & 1u)       ? -1000.f : sacc[nt][2] * 0.125f;
            float s3 = ((wb >> (sh + 1)) & 1u) ? -1000.f : sacc[nt][3] * 0.125f;
            sacc[nt][0] = s0; sacc[nt][1] = s1; sacc[nt][2] = s2; sacc[nt][3] = s3;
            rmax0 = fmaxf(rmax0, fmaxf(s0, s1));
            rmax1 = fmaxf(rmax1, fmaxf(s2, s3));
        }
        rmax0 = fmaxf(rmax0, __shfl_xor_sync(0xffffffffu, rmax0, 1));
        rmax0 = fmaxf(rmax0, __shfl_xor_sync(0xffffffffu, rmax0, 2));
        rmax1 = fmaxf(rmax1, __shfl_xor_sync(0xffffffffu, rmax1, 1));
        rmax1 = fmaxf(rmax1, __shfl_xor_sync(0xffffffffu, rmax1, 2));
        float mn0 = fmaxf(m0, rmax0);
        float mn1 = fmaxf(m1, rmax1);

        float rs0 = 0.f, rs1 = 0.f;
        #pragma unroll
        for (int nt = 0; nt < 8; nt++) {
            float p0 = __expf(sacc[nt][0] - mn0);
            float p1 = __expf(sacc[nt][1] - mn0);
            float p2 = __expf(sacc[nt][2] - mn1);
            float p3 = __expf(sacc[nt][3] - mn1);
            rs0 += p0 + p1;
            rs1 += p2 + p3;
            sacc[nt][0] = f2tff(p0); sacc[nt][1] = f2tff(p1);
            sacc[nt][2] = f2tff(p2); sacc[nt][3] = f2tff(p3);
        }
        rs0 += __shfl_xor_sync(0xffffffffu, rs0, 1);
        rs0 += __shfl_xor_sync(0xffffffffu, rs0, 2);
        rs1 += __shfl_xor_sync(0xffffffffu, rs1, 1);
        rs1 += __shfl_xor_sync(0xffffffffu, rs1, 2);

        float al0 = __expf(m0 - mn0);
        float al1 = __expf(m1 - mn1);
        l0 = l0 * al0 + rs0;
        l1 = l1 * al1 + rs1;
        m0 = mn0; m1 = mn1;
        #pragma unroll
        for (int nt = 0; nt < 8; nt++) {
            oacc[nt][0] *= al0; oacc[nt][1] *= al0;
            oacc[nt][2] *= al1; oacc[nt][3] *= al1;
        }

        // O += P @ V. P C-fragments -> A-fragments via warp shuffles.
        #pragma unroll
        for (int kk = 0; kk < 8; kk++) {
            int src = g * 4 + (tg >> 1);
            float p0 = __shfl_sync(0xffffffffu, sacc[kk][0], src);
            float p1 = __shfl_sync(0xffffffffu, sacc[kk][1], src);
            float p2 = __shfl_sync(0xffffffffu, sacc[kk][2], src);
            float p3 = __shfl_sync(0xffffffffu, sacc[kk][3], src);
            float u0 = __shfl_sync(0xffffffffu, sacc[kk][0], src + 2);
            float u1 = __shfl_sync(0xffffffffu, sacc[kk][1], src + 2);
            float u2 = __shfl_sync(0xffffffffu, sacc[kk][2], src + 2);
            float u3 = __shfl_sync(0xffffffffu, sacc[kk][3], src + 2);
            bool odd = tg & 1;
            uint32_t a0 = __float_as_uint(odd ? p1 : p0);
            uint32_t a1 = __float_as_uint(odd ? p3 : p2);
            uint32_t a2 = __float_as_uint(odd ? u1 : u0);
            uint32_t a3 = __float_as_uint(odd ? u3 : u2);
            #pragma unroll
            for (int nt = 0; nt < 8; nt++) {
                uint32_t b0 = __float_as_uint(Vcur[(kk * 8 + tg) * 72 + nt * 8 + g]);
                uint32_t b1 = __float_as_uint(Vcur[(kk * 8 + tg + 4) * 72 + nt * 8 + g]);
                mma_m16n8k8(oacc[nt], a0, a1, a2, a3, b0, b1);
            }
        }
        __syncthreads();   // all reads of buffers done before next issue overwrites
    }

    float inv0 = 1.f / l0;
    float inv1 = 1.f / l1;
    #pragma unroll
    for (int nt = 0; nt < 8; nt++) {
        int r = q0 + r0l;
        int c = h * DK_ + nt * 8 + 2 * tg;
        float2 v0 = make_float2(oacc[nt][0] * inv0, oacc[nt][1] * inv0);
        float2 v1 = make_float2(oacc[nt][2] * inv1, oacc[nt][3] * inv1);
        *(float2*)(X + ((size_t)(b * S_ + r)) * D_ + c)     = v0;
        *(float2*)(X + ((size_t)(b * S_ + r + 8)) * D_ + c) = v1;
    }
}

extern "C" void kernel_launch(void* const* d_in, const int* in_sizes, int n_in,
                              void* d_out, int out_size) {
    (void)in_sizes; (void)n_in; (void)out_size;
    const float* query = (const float*)d_in[0];
    const float* key   = (const float*)d_in[1];
    const float* value = (const float*)d_in[2];
    const int*   mask  = (const int*)d_in[3];
    const float* Wq = (const float*)d_in[4];
    const float* bq = (const float*)d_in[5];
    const float* Wk = (const float*)d_in[6];
    const float* bk = (const float*)d_in[7];
    const float* Wv = (const float*)d_in[8];
    const float* bv = (const float*)d_in[9];
    const float* Wo = (const float*)d_in[10];
    const float* bo = (const float*)d_in[11];
    float* out = (float*)d_out;

    float *pQ, *pK, *pV, *pX;
    uint32_t* pMb;
    cudaGetSymbolAddress((void**)&pQ, g_Q);
    cudaGetSymbolAddress((void**)&pK, g_K);
    cudaGetSymbolAddress((void**)&pV, g_V);
    cudaGetSymbolAddress((void**)&pX, g_X);
    cudaGetSymbolAddress((void**)&pMb, g_Mb);

    static bool attr_done = false;
    if (!attr_done) {
        cudaFuncSetAttribute(gemm3_nt_bias,
                             cudaFuncAttributeMaxDynamicSharedMemorySize, GEMM_SMEM_BYTES);
        cudaFuncSetAttribute(attn_kernel,
                             cudaFuncAttributeMaxDynamicSharedMemorySize, ATTN_SMEM_BYTES);
        attr_done = true;
    }

    const int M = B_ * S_;

    // mask bit-pack
    pack_mask_kernel<<<(B_ * S_ * S_) / 256, 256>>>(mask, pMb);

    // fused QKV projections (round outputs to tf32 for the attention MMAs)
    dim3 gq(D_ / 128, M / 128, 3);
    gemm3_nt_bias<<<gq, 256, GEMM_SMEM_BYTES>>>(
        query, key, value, Wq, Wk, Wv, bq, bk, bv, pQ, pK, pV, M, D_, D_, 1);

    attn_kernel<<<dim3(H_, S_ / 64, B_), 128, ATTN_SMEM_BYTES>>>(pQ, pK, pV, pMb, pX);

    // output projection (full fp32 out)
    dim3 go(D_ / 128, M / 128, 1);
    gemm3_nt_bias<<<go, 256, GEMM_SMEM_BYTES>>>(
        pX, pX, pX, Wo, Wo, Wo, bo, bo, bo, out, out, out, M, D_, D_, 0);
}